// round 7
// baseline (speedup 1.0000x reference)
#include <cuda_runtime.h>

#define Bz 4
#define Nz 8192
#define Mz 2048
#define Kz 20
#define Cz 64
#define PTS (Bz*Mz*Kz)   // 163840
#define NSLICE 8
#define SLEN 1024

typedef unsigned long long ull;

// ---------------- packed f32x2 helpers (sm_100+: add/mul/fma only) ----------------
__device__ __forceinline__ ull PK(float lo, float hi) {
    ull r; asm("mov.b64 %0, {%1,%2};" : "=l"(r) : "f"(lo), "f"(hi)); return r;
}
__device__ __forceinline__ void UPK(ull v, float& lo, float& hi) {
    asm("mov.b64 {%0,%1}, %2;" : "=f"(lo), "=f"(hi) : "l"(v));
}
__device__ __forceinline__ ull ADD2(ull a, ull b) {
    ull r; asm("add.rn.f32x2 %0, %1, %2;" : "=l"(r) : "l"(a), "l"(b)); return r;
}
__device__ __forceinline__ ull MUL2(ull a, ull b) {
    ull r; asm("mul.rn.f32x2 %0, %1, %2;" : "=l"(r) : "l"(a), "l"(b)); return r;
}
__device__ __forceinline__ ull FMA2(ull a, ull b, ull c) {
    ull r; asm("fma.rn.f32x2 %0, %1, %2, %3;" : "=l"(r) : "l"(a), "l"(b), "l"(c)); return r;
}
// order-preserving float<->uint maps (for REDUX min/max over signed floats)
__device__ __forceinline__ unsigned F2U(float f) {
    unsigned u = __float_as_uint(f);
    return u ^ (unsigned)(((int)u >> 31) | 0x80000000);
}
__device__ __forceinline__ float U2F(unsigned m) {
    unsigned u = (m & 0x80000000u) ? (m ^ 0x80000000u) : ~m;
    return __uint_as_float(u);
}

// ---------------- scratch (static device globals; no allocation) ----------------
__device__ float4 g_q[Bz*Mz];                    // sampled pts: x,y,z,|q|^2
__device__ int    g_nidx[Bz*Mz*Kz];              // final knn indices
__device__ float  g_kd[Bz*Mz*NSLICE*Kz];         // per-slice partial top-20 dists
__device__ int    g_ki[Bz*Mz*NSLICE*Kz];         // per-slice partial top-20 idx
__device__ float  g_x1[(size_t)PTS*Cz];          // ~42MB
__device__ float  g_x2[(size_t)PTS*Cz];          // ~42MB
__device__ double g_sum[2*Cz];                   // per-channel sum / sumsq (re-zeroed by bnfin)
__device__ float  g_aff[3*2*Cz];                 // per-stage BN affine: a[64], c[64]
__device__ float  g_sx[Bz*Nz];                   // Morton-sorted coords
__device__ float  g_sy[Bz*Nz];
__device__ float  g_sz[Bz*Nz];
__device__ int    g_sid[Bz*Nz];                  // sorted -> original index

// ================= counting sort by 9-bit Morton cell (8x8x8 grid) =================
__device__ __forceinline__ int sp3(int v) { return (v&1) | ((v&2)<<2) | ((v&4)<<4); }

__global__ void __launch_bounds__(512) sort_kernel(const float* __restrict__ p) {
    __shared__ int hist[512];
    __shared__ int base[512];
    const int b = blockIdx.x, tid = threadIdx.x;
    const float* pb = p + (size_t)b*Nz*3;
    hist[tid] = 0;
    __syncthreads();
    int codes[16];
#pragma unroll
    for (int s = 0; s < 16; ++s) {
        int i = tid + s*512;
        float x = pb[3*i], y = pb[3*i+1], z = pb[3*i+2];
        int qx = min(7, max(0, __float2int_rd((x + 2.8f) * 1.4285715f)));
        int qy = min(7, max(0, __float2int_rd((y + 2.8f) * 1.4285715f)));
        int qz = min(7, max(0, __float2int_rd((z + 2.8f) * 1.4285715f)));
        codes[s] = (sp3(qx)<<2) | (sp3(qy)<<1) | sp3(qz);
        atomicAdd(&hist[codes[s]], 1);
    }
    __syncthreads();
    if (tid < 32) {
        int v[16]; int tot = 0;
#pragma unroll
        for (int k = 0; k < 16; ++k) v[k] = hist[tid*16 + k];
#pragma unroll
        for (int k = 0; k < 16; ++k) { int x = v[k]; v[k] = tot; tot += x; }
        int run = tot;
#pragma unroll
        for (int o = 1; o < 32; o <<= 1) {
            int u = __shfl_up_sync(0xffffffffu, run, o);
            if (tid >= o) run += u;
        }
        int excl = run - tot;
#pragma unroll
        for (int k = 0; k < 16; ++k) base[tid*16 + k] = v[k] + excl;
    }
    __syncthreads();
#pragma unroll
    for (int s = 0; s < 16; ++s) {
        int i = tid + s*512;
        int pos = atomicAdd(&base[codes[s]], 1);
        g_sx[b*Nz+pos] = pb[3*i];
        g_sy[b*Nz+pos] = pb[3*i+1];
        g_sz[b*Nz+pos] = pb[3*i+2];
        g_sid[b*Nz+pos] = i;
    }
}

// ===== FPS v3: 256 thr, 8 warps x 4 warp-private chunks of 256, exact bbox pruning ==========
extern __shared__ float fps_dyn[];   // sx[8192], sy[8192], sz[8192], sid[8192] = 128kB

__global__ void __launch_bounds__(256,1) fps_kernel(const float* __restrict__ p) {
    float* sx = fps_dyn; float* sy = fps_dyn + Nz; float* sz = fps_dyn + 2*Nz;
    int*   sid = (int*)(fps_dyn + 3*Nz);
    __shared__ float s_bb[32][8];
    __shared__ unsigned s_bv[8];
    __shared__ unsigned s_wi[2];
    const int b = blockIdx.x, tid = threadIdx.x;
    const int w = tid >> 5, lane = tid & 31;
    const float* pb = p + (size_t)b*Nz*3;

    for (int i = tid; i < Nz; i += 256) {
        sx[i] = g_sx[b*Nz+i]; sy[i] = g_sy[b*Nz+i]; sz[i] = g_sz[b*Nz+i]; sid[i] = g_sid[b*Nz+i];
    }
    if (tid == 0) { s_wi[0] = 0xFFFFFFFFu; s_wi[1] = 0xFFFFFFFFu; }
    __syncthreads();

    // warp w owns sorted range [w*1024, (w+1)*1024) = chunks 4w..4w+3 (256 pts each)
    // u-block u (0..15): chunk c=u>>2; indices wbase + c*256 + (u&3)*64 + 2*lane (+1)
    const int wbase = w*1024;
    ull px2[16], py2[16], pz2[16];
    float dd[32];
#pragma unroll
    for (int u = 0; u < 16; ++u) {
        int i0 = wbase + (u>>2)*256 + (u&3)*64 + 2*lane;
        px2[u] = PK(sx[i0], sx[i0+1]);
        py2[u] = PK(sy[i0], sy[i0+1]);
        pz2[u] = PK(sz[i0], sz[i0+1]);
        dd[2*u] = 1e10f; dd[2*u+1] = 1e10f;
    }
    // per-chunk bbox via REDUX on order-mapped bits
    float cmx[4];
#pragma unroll
    for (int c = 0; c < 4; ++c) {
        unsigned xl=0xFFFFFFFFu, xh=0, yl=0xFFFFFFFFu, yh=0, zl=0xFFFFFFFFu, zh=0;
#pragma unroll
        for (int j = 0; j < 4; ++j) {
            int u = 4*c + j; float a0, a1; unsigned m0, m1;
            UPK(px2[u],a0,a1); m0=F2U(a0); m1=F2U(a1); xl=umin(xl,umin(m0,m1)); xh=umax(xh,umax(m0,m1));
            UPK(py2[u],a0,a1); m0=F2U(a0); m1=F2U(a1); yl=umin(yl,umin(m0,m1)); yh=umax(yh,umax(m0,m1));
            UPK(pz2[u],a0,a1); m0=F2U(a0); m1=F2U(a1); zl=umin(zl,umin(m0,m1)); zh=umax(zh,umax(m0,m1));
        }
        xl = __reduce_min_sync(0xffffffffu, xl); xh = __reduce_max_sync(0xffffffffu, xh);
        yl = __reduce_min_sync(0xffffffffu, yl); yh = __reduce_max_sync(0xffffffffu, yh);
        zl = __reduce_min_sync(0xffffffffu, zl); zh = __reduce_max_sync(0xffffffffu, zh);
        if (lane == 0) {
            float* bb = s_bb[4*w+c];
            bb[0]=U2F(xl); bb[1]=U2F(xh); bb[2]=U2F(yl); bb[3]=U2F(yh); bb[4]=U2F(zl); bb[5]=U2F(zh);
        }
        cmx[c] = 1e10f;
    }
    float lx = pb[0], ly = pb[1], lz = pb[2];
    if (tid == 0) {
        float qq = __fadd_rn(__fadd_rn(__fmul_rn(lx,lx), __fmul_rn(ly,ly)), __fmul_rn(lz,lz));
        g_q[b*Mz] = make_float4(lx, ly, lz, qq);
    }
    __syncthreads();

    for (int t = 1; t < Mz; ++t) {
        // lanes 0-3: exact-safe prune test for this warp's 4 chunks
        bool act = false;
        {
            const float* bb = s_bb[4*w + (lane & 3)];
            float ex = fmaxf(fmaxf(bb[0]-lx, lx-bb[1]), 0.f);
            float ey = fmaxf(fmaxf(bb[2]-ly, ly-bb[3]), 0.f);
            float ez = fmaxf(fmaxf(bb[4]-lz, lz-bb[5]), 0.f);
            float lb = (ex*ex + ey*ey + ez*ez) * 0.999f;   // huge margin vs <=4-ulp rounding
            float cl = (lane==0) ? cmx[0] : (lane==1) ? cmx[1] : (lane==2) ? cmx[2] : cmx[3];
            act = (lane < 4) && (lb < cl);
        }
        const unsigned amask = __ballot_sync(0xffffffffu, act);
        const ull nx2 = PK(-lx,-lx), ny2 = PK(-ly,-ly), nz2 = PK(-lz,-lz);
#pragma unroll
        for (int c = 0; c < 4; ++c) {
            if (amask & (1u << c)) {                   // warp-uniform
                float cm = 0.0f;
#pragma unroll
                for (int j = 0; j < 4; ++j) {
                    int u = 4*c + j;
                    // exact rn order: ((dx*dx + dy*dy) + dz*dz); x+(-l) == x-l bitwise
                    ull dx2 = ADD2(px2[u], nx2);
                    ull dy2 = ADD2(py2[u], ny2);
                    ull dz2 = ADD2(pz2[u], nz2);
                    ull d2  = ADD2(ADD2(MUL2(dx2,dx2), MUL2(dy2,dy2)), MUL2(dz2,dz2));
                    float d0, d1; UPK(d2, d0, d1);
                    float n0 = fminf(dd[2*u],   d0);
                    float n1 = fminf(dd[2*u+1], d1);
                    dd[2*u] = n0; dd[2*u+1] = n1;
                    cm = fmaxf(cm, fmaxf(n0, n1));
                }
                cmx[c] = __uint_as_float(__reduce_max_sync(0xffffffffu, __float_as_uint(cm)));
            }
        }
        // warp best = max of 4 warp-uniform chunk maxima (nonneg floats: bits monotone)
        unsigned b0 = __float_as_uint(cmx[0]), b1 = __float_as_uint(cmx[1]);
        unsigned b2 = __float_as_uint(cmx[2]), b3 = __float_as_uint(cmx[3]);
        unsigned wb = umax(umax(b0,b1), umax(b2,b3));
        if (lane == 0) s_bv[w] = wb;
        __syncthreads();                               // bar 1
        unsigned gb = s_bv[0];
#pragma unroll
        for (int k = 1; k < 8; ++k) gb = umax(gb, s_bv[k]);
        const float gv = __uint_as_float(gb);
        const int buf = t & 1;
        if (tid == 0) s_wi[buf^1] = 0xFFFFFFFFu;       // reset next-step buffer
        // winner scan: only chunks whose max equals global max; tie -> lowest ORIGINAL index
#pragma unroll
        for (int c = 0; c < 4; ++c) {
            if (__float_as_uint(cmx[c]) == gb) {       // warp-uniform
#pragma unroll
                for (int j = 0; j < 4; ++j) {
                    int u = 4*c + j;
                    int i0 = wbase + c*256 + j*64 + 2*lane;
                    if (dd[2*u]   == gv) atomicMin(&s_wi[buf], ((unsigned)sid[i0]  <<13) | (unsigned)i0);
                    if (dd[2*u+1] == gv) atomicMin(&s_wi[buf], ((unsigned)sid[i0+1]<<13) | (unsigned)(i0+1));
                }
            }
        }
        __syncthreads();                               // bar 2
        const int spos = (int)(s_wi[buf] & 8191u);
        lx = sx[spos]; ly = sy[spos]; lz = sz[spos];
        if (tid == 0) {
            float qq = __fadd_rn(__fadd_rn(__fmul_rn(lx,lx), __fmul_rn(ly,ly)), __fmul_rn(lz,lz));
            g_q[b*Mz + t] = make_float4(lx, ly, lz, qq);
        }
    }
}

// ================= kNN: 256 queries/block x 8 point-slices, packed distances =================
__global__ void __launch_bounds__(256) knn_kernel(const float* __restrict__ p) {
    __shared__ ull spt[SLEN/2][4];      // per pair: x2,y2,z2,w2 (16kB)
    const int tid = threadIdx.x;
    const int qi = blockIdx.x*256 + tid;
    const int b  = qi >> 11;
    const float* pb = p + (size_t)b*Nz*3;
    const int t0 = blockIdx.y * SLEN;

    for (int i = tid; i < SLEN/2; i += 256) {
        int i0 = t0 + 2*i, i1 = i0 + 1;
        float x0 = pb[3*i0+0], y0 = pb[3*i0+1], z0 = pb[3*i0+2];
        float x1 = pb[3*i1+0], y1 = pb[3*i1+1], z1 = pb[3*i1+2];
        float w0 = __fadd_rn(__fadd_rn(__fmul_rn(x0,x0), __fmul_rn(y0,y0)), __fmul_rn(z0,z0));
        float w1 = __fadd_rn(__fadd_rn(__fmul_rn(x1,x1), __fmul_rn(y1,y1)), __fmul_rn(z1,z1));
        spt[i][0] = PK(x0,x1); spt[i][1] = PK(y0,y1);
        spt[i][2] = PK(z0,z1); spt[i][3] = PK(w0,w1);
    }
    __syncthreads();

    const float4 q = g_q[qi];
    const ull qx2 = PK(q.x,q.x), qy2 = PK(q.y,q.y), qz2 = PK(q.z,q.z);
    const ull qw2 = PK(q.w,q.w), n2 = PK(-2.0f,-2.0f);

    float nd[Kz]; int ni[Kz];
#pragma unroll
    for (int j = 0; j < Kz; ++j) { nd[j] = 1e30f; ni[j] = 0; }
    float wk = 1e30f;

    for (int u = 0; u < SLEN/2; ++u) {
        const ulonglong2* r = (const ulonglong2*)spt[u];
        ulonglong2 r0 = r[0], r1 = r[1];
        // d = (qq + pp) + (-2)*(((qx*px + qy*py) + qz*pz))  -- bitwise == reference order
        ull m1 = MUL2(qx2, r0.x);
        ull m2 = MUL2(qy2, r0.y);
        ull a1 = ADD2(m1, m2);
        ull m3 = MUL2(qz2, r1.x);
        ull a2 = ADD2(a1, m3);
        ull a3 = ADD2(qw2, r1.y);
        ull m4 = MUL2(a2, n2);
        ull d2 = ADD2(a3, m4);
        float d0, d1; UPK(d2, d0, d1);
        if (d0 < wk) {
            float cd = d0; int ci = t0 + 2*u;
#pragma unroll
            for (int j = 0; j < Kz; ++j)
                if (cd < nd[j]) { float td = nd[j]; int ti = ni[j]; nd[j] = cd; ni[j] = ci; cd = td; ci = ti; }
            wk = nd[Kz-1];
        }
        if (d1 < wk) {
            float cd = d1; int ci = t0 + 2*u + 1;
#pragma unroll
            for (int j = 0; j < Kz; ++j)
                if (cd < nd[j]) { float td = nd[j]; int ti = ni[j]; nd[j] = cd; ni[j] = ci; cd = td; ci = ti; }
            wk = nd[Kz-1];
        }
    }
    const size_t base = ((size_t)qi*NSLICE + blockIdx.y)*Kz;
#pragma unroll
    for (int j = 0; j < Kz; ++j) { g_kd[base+j] = nd[j]; g_ki[base+j] = ni[j]; }
}

// ---- exact 8-way merge of per-slice sorted (d, idx) lists -> global top-20 ----
__global__ void __launch_bounds__(256) kmerge_kernel() {
    const int qi = blockIdx.x*256 + threadIdx.x;
    float dc[NSLICE]; int ic[NSLICE]; int h[NSLICE];
#pragma unroll
    for (int s = 0; s < NSLICE; ++s) {
        size_t base = ((size_t)qi*NSLICE + s)*Kz;
        dc[s] = g_kd[base]; ic[s] = g_ki[base]; h[s] = 0;
    }
    for (int j = 0; j < Kz; ++j) {
        int bs = 0;
#pragma unroll
        for (int s = 1; s < NSLICE; ++s)
            if (dc[s] < dc[bs] || (dc[s] == dc[bs] && ic[s] < ic[bs])) bs = s;
        g_nidx[(size_t)qi*Kz + j] = ic[bs];
        h[bs]++;
        if (h[bs] < Kz) {
            size_t off = ((size_t)qi*NSLICE + bs)*Kz + h[bs];
            dc[bs] = g_kd[off]; ic[bs] = g_ki[off];
        } else { dc[bs] = 3.0e38f; ic[bs] = 0x7FFFFFFF; }
    }
}

// ====== conv1: 1 thread = 1 group-point, [6->64] matvec + leaky + fused BN stats ======
__global__ void __launch_bounds__(128) conv1_kernel(const float* __restrict__ p,
                                                    const float* __restrict__ W1) {
    __shared__ float sWc[64][8];        // [c][j], 2 broadcast loads per channel
    __shared__ float so[128*68];        // staged outputs (68-pad: 16B-aligned rows)
    __shared__ float sps[2][64], sqs[2][64];
    const int tid = threadIdx.x;
    if (tid < 64) {
#pragma unroll
        for (int j = 0; j < 6; ++j) sWc[tid][j] = W1[tid*6 + j];
        sWc[tid][6] = 0.f; sWc[tid][7] = 0.f;
    }
    const int gp0 = blockIdx.x * 128;
    const int gp = gp0 + tid;
    const int m = (gp / Kz) % Mz;
    const int b = gp / (Kz*Mz);
    const int nid = g_nidx[gp];
    const float* pr = p + ((size_t)b*Nz + nid)*3;
    float gx = pr[0], gy = pr[1], gz = pr[2];
    float4 q = g_q[b*Mz + m];
    float f0 = __fsub_rn(gx, q.x), f1 = __fsub_rn(gy, q.y), f2 = __fsub_rn(gz, q.z);
    __syncthreads();
#pragma unroll 4
    for (int c = 0; c < 64; ++c) {
        float4 w0 = *(const float4*)&sWc[c][0];
        float2 w1 = *(const float2*)&sWc[c][4];
        float acc = w0.x * f0;
        acc = fmaf(w0.y, f1, acc);
        acc = fmaf(w0.z, f2, acc);
        acc = fmaf(w0.w, gx, acc);
        acc = fmaf(w1.x, gy, acc);
        acc = fmaf(w1.y, gz, acc);
        so[tid*68 + c] = (acc >= 0.f) ? acc : 0.2f*acc;
    }
    __syncthreads();
    // fused BN stats partials
    {
        int c = tid & 63, h = tid >> 6;
        float s = 0.f, s2 = 0.f;
#pragma unroll 8
        for (int r = h*64; r < h*64 + 64; ++r) {
            float v = so[r*68 + c];
            s += v; s2 = fmaf(v, v, s2);
        }
        sps[h][c] = s; sqs[h][c] = s2;
    }
    __syncthreads();
    if (tid < 64) {
        atomicAdd(&g_sum[tid],      (double)(sps[0][tid] + sps[1][tid]));
        atomicAdd(&g_sum[64 + tid], (double)(sqs[0][tid] + sqs[1][tid]));
    }
    // coalesced writeout
    for (int idx = tid; idx < 2048; idx += 128) {
        int row = idx >> 4, sg = idx & 15;
        float4 v = *(const float4*)&so[row*68 + sg*4];
        *(float4*)(g_x1 + (size_t)(gp0 + row)*64 + sg*4) = v;
    }
}

// ======== conv2/3: FFMA2 [64->64] matvec, 4 pts/thread, fused BN stats ========
#define WJ 10
#define WCG (64*WJ + 4)
__global__ void __launch_bounds__(128) conv_kernel(int in_sel, const float* __restrict__ W,
                                                   int aff_stage) {
    const float* xin = in_sel ? g_x2 : g_x1;
    float*      xout = in_sel ? g_x1 : g_x2;
    __shared__ ull  sw[4*WCG];
    __shared__ float sx[128][65];
    __shared__ float sa[64], sc[64];
    __shared__ float ssumW[4*64], ssqW[4*64];
    const int tid = threadIdx.x;
    const int ww = tid >> 5, lane = tid & 31;

    for (int k = tid; k < 2048; k += 128) {
        int cgk = k >> 9, rem = k & 511, j = rem >> 3, qq = rem & 7;
        int c0 = cgk*16 + 2*qq;
        sw[cgk*WCG + j*WJ + qq] = PK(W[c0*64 + j], W[(c0+1)*64 + j]);
    }
    if (tid < 64) {
        sa[tid] = g_aff[aff_stage*128 + tid];
        sc[tid] = g_aff[aff_stage*128 + 64 + tid];
    }
    __syncthreads();
    const int p0 = blockIdx.x * 128;
    for (int idx = tid; idx < 8192; idx += 128) {
        int j = idx & 63;
        float v = xin[(size_t)p0*64 + idx];
        sx[idx >> 6][j] = fmaf(sa[j], v, sc[j]);
    }
    __syncthreads();

    const int ptb = tid >> 2, cg = tid & 3;
    const ull* wbase = &sw[cg*WCG];
    ull acc[4][8];
#pragma unroll
    for (int k = 0; k < 4; ++k)
#pragma unroll
        for (int qq = 0; qq < 8; ++qq) acc[k][qq] = 0ull;

    for (int j = 0; j < 64; ++j) {
        const ulonglong2* wr = (const ulonglong2*)(wbase + j*WJ);
        ulonglong2 w01 = wr[0], w23 = wr[1], w45 = wr[2], w67 = wr[3];
        ull wv[8] = {w01.x, w01.y, w23.x, w23.y, w45.x, w45.y, w67.x, w67.y};
#pragma unroll
        for (int k = 0; k < 4; ++k) {
            float xv = sx[ptb + 32*k][j];
            ull xv2 = PK(xv, xv);
#pragma unroll
            for (int qq = 0; qq < 8; ++qq)
                acc[k][qq] = FMA2(wv[qq], xv2, acc[k][qq]);
        }
    }
    float sacc[16], sqacc[16];
#pragma unroll
    for (int i = 0; i < 16; ++i) { sacc[i] = 0.f; sqacc[i] = 0.f; }
#pragma unroll
    for (int k = 0; k < 4; ++k) {
        float o[16];
#pragma unroll
        for (int qq = 0; qq < 8; ++qq) {
            float lo, hi; UPK(acc[k][qq], lo, hi);
            o[2*qq]   = (lo >= 0.f) ? lo : 0.2f*lo;
            o[2*qq+1] = (hi >= 0.f) ? hi : 0.2f*hi;
        }
#pragma unroll
        for (int i = 0; i < 16; ++i) {
            sacc[i] += o[i];
            sqacc[i] = fmaf(o[i], o[i], sqacc[i]);
        }
        float4* op = (float4*)(xout + (size_t)(p0 + ptb + 32*k)*64 + cg*16);
#pragma unroll
        for (int v4 = 0; v4 < 4; ++v4)
            op[v4] = make_float4(o[4*v4], o[4*v4+1], o[4*v4+2], o[4*v4+3]);
    }
    // reduce over the 8 same-cg lanes in this warp (xor 4,8,16)
#pragma unroll
    for (int o = 4; o <= 16; o <<= 1) {
#pragma unroll
        for (int i = 0; i < 16; ++i) {
            sacc[i]  += __shfl_xor_sync(0xffffffffu, sacc[i],  o);
            sqacc[i] += __shfl_xor_sync(0xffffffffu, sqacc[i], o);
        }
    }
    if (lane < 4) {
#pragma unroll
        for (int i = 0; i < 16; ++i) {
            ssumW[ww*64 + lane*16 + i] = sacc[i];
            ssqW [ww*64 + lane*16 + i] = sqacc[i];
        }
    }
    __syncthreads();
    if (tid < 64) {
        float S = 0.f, Q = 0.f;
#pragma unroll
        for (int v = 0; v < 4; ++v) { S += ssumW[v*64 + tid]; Q += ssqW[v*64 + tid]; }
        atomicAdd(&g_sum[tid],      (double)S);
        atomicAdd(&g_sum[64 + tid], (double)Q);
    }
}

// ---------------- BN finalize: affine a,c; re-zeroes accumulators for next stage/replay ------
__global__ void bnfin_kernel(int stage, const float* __restrict__ g, const float* __restrict__ bb) {
    const int c = threadIdx.x;   // 64 threads
    const double cnt = (double)PTS;
    double mean = g_sum[c] / cnt;
    double var  = g_sum[64 + c] / cnt - mean*mean;
    double inv  = 1.0 / sqrt(var + 1e-5);
    float a  = (float)((double)g[c] * inv);
    float cc = (float)((double)bb[c] - (double)a * mean);
    g_aff[stage*128 + c]      = a;
    g_aff[stage*128 + 64 + c] = cc;
    g_sum[c] = 0.0; g_sum[64 + c] = 0.0;
}

// ---------------- final: apply BN3 affine, max over K ----------------
__global__ void __launch_bounds__(256) maxk_kernel(float* __restrict__ out) {
    const int t = blockIdx.x*256 + threadIdx.x;      // [0, B*M*64)
    const int c = t & 63;
    const int m = (t >> 6) & 2047;
    const int b = t >> 17;
    const float* base = g_x1 + ((size_t)(b*Mz + m)*Kz)*64 + c;
    const float a  = g_aff[2*128 + c];
    const float cc = g_aff[2*128 + 64 + c];
    float mx = -1e30f;
#pragma unroll
    for (int k = 0; k < Kz; ++k) {
        float v = fmaf(a, base[(size_t)k*64], cc);
        mx = fmaxf(mx, v);
    }
    out[((size_t)(b*64 + c))*Mz + m] = mx;
}

// ---------------- launch ----------------
extern "C" void kernel_launch(void* const* d_in, const int* in_sizes, int n_in,
                              void* d_out, int out_size) {
    (void)in_sizes; (void)n_in; (void)out_size;
    const float* p  = (const float*)d_in[0];
    const float* W1 = (const float*)d_in[1];
    const float* g1 = (const float*)d_in[2];
    const float* b1 = (const float*)d_in[3];
    const float* W2 = (const float*)d_in[4];
    const float* g2 = (const float*)d_in[5];
    const float* b2 = (const float*)d_in[6];
    const float* W3 = (const float*)d_in[7];
    const float* g3 = (const float*)d_in[8];
    const float* b3 = (const float*)d_in[9];
    float* out = (float*)d_out;

    cudaFuncSetAttribute(fps_kernel, cudaFuncAttributeMaxDynamicSharedMemorySize, 4*Nz*4);

    sort_kernel<<<Bz, 512>>>(p);
    fps_kernel<<<Bz, 256, 4*Nz*4>>>(p);
    knn_kernel<<<dim3((Bz*Mz)/256, NSLICE), 256>>>(p);
    kmerge_kernel<<<(Bz*Mz)/256, 256>>>();
    conv1_kernel<<<PTS/128, 128>>>(p, W1);
    bnfin_kernel<<<1, 64>>>(0, g1, b1);
    conv_kernel<<<PTS/128, 128>>>(0, W2, 0);
    bnfin_kernel<<<1, 64>>>(1, g2, b2);
    conv_kernel<<<PTS/128, 128>>>(1, W3, 1);
    bnfin_kernel<<<1, 64>>>(2, g3, b3);
    maxk_kernel<<<(Bz*Mz*Cz)/256, 256>>>(out);
}

// round 8
// speedup vs baseline: 1.2123x; 1.2123x over previous
#include <cuda_runtime.h>

#define Bz 4
#define Nz 8192
#define Mz 2048
#define Kz 20
#define Cz 64
#define PTS (Bz*Mz*Kz)   // 163840
#define NSLICE 8
#define SLEN 1024

typedef unsigned long long ull;

// ---------------- packed f32x2 helpers (sm_100+: add/mul/fma only) ----------------
__device__ __forceinline__ ull PK(float lo, float hi) {
    ull r; asm("mov.b64 %0, {%1,%2};" : "=l"(r) : "f"(lo), "f"(hi)); return r;
}
__device__ __forceinline__ void UPK(ull v, float& lo, float& hi) {
    asm("mov.b64 {%0,%1}, %2;" : "=f"(lo), "=f"(hi) : "l"(v));
}
__device__ __forceinline__ ull ADD2(ull a, ull b) {
    ull r; asm("add.rn.f32x2 %0, %1, %2;" : "=l"(r) : "l"(a), "l"(b)); return r;
}
__device__ __forceinline__ ull MUL2(ull a, ull b) {
    ull r; asm("mul.rn.f32x2 %0, %1, %2;" : "=l"(r) : "l"(a), "l"(b)); return r;
}
__device__ __forceinline__ ull FMA2(ull a, ull b, ull c) {
    ull r; asm("fma.rn.f32x2 %0, %1, %2, %3;" : "=l"(r) : "l"(a), "l"(b), "l"(c)); return r;
}

// ---------------- scratch (static device globals; no allocation) ----------------
__device__ float4 g_q[Bz*Mz];                    // sampled pts: x,y,z,|q|^2
__device__ int    g_nidx[Bz*Mz*Kz];              // final knn indices
__device__ float  g_kd[Bz*Mz*NSLICE*Kz];         // per-slice partial top-20 dists
__device__ int    g_ki[Bz*Mz*NSLICE*Kz];         // per-slice partial top-20 idx
__device__ float  g_x1[(size_t)PTS*Cz];          // ~42MB
__device__ float  g_x2[(size_t)PTS*Cz];          // ~42MB
__device__ double g_sum[2*Cz];                   // per-channel sum / sumsq (re-zeroed by bnfin)
__device__ float  g_aff[3*2*Cz];                 // per-stage BN affine: a[64], c[64]

// ===== FPS: 256 thr/batch, 32 pts/thread, packed FMA distances, REDUX warp max ===============
extern __shared__ float fps_sm[];   // spx[8192], spy[8192], spz[8192] = 96kB

__global__ void __launch_bounds__(256,1) fps_kernel(const float* __restrict__ p) {
    const int b = blockIdx.x;
    const int tid = threadIdx.x;
    const float* pb = p + (size_t)b*Nz*3;
    float* spx = fps_sm; float* spy = fps_sm + Nz; float* spz = fps_sm + 2*Nz;
    __shared__ unsigned s_bv[8];
    __shared__ unsigned s_wi[2];

    for (int i = tid; i < Nz; i += 256) {
        spx[i] = pb[3*i+0]; spy[i] = pb[3*i+1]; spz[i] = pb[3*i+2];
    }
    if (tid == 0) { s_wi[0] = 0xFFFFFFFFu; s_wi[1] = 0xFFFFFFFFu; }
    __syncthreads();

    // register-resident points as 16 packed pairs; element u covers indices tid+(2u)*256, tid+(2u+1)*256
    ull px2[16], py2[16], pz2[16];
    float dd[32];
#pragma unroll
    for (int u = 0; u < 16; ++u) {
        int i0 = tid + (2*u)*256, i1 = i0 + 256;
        px2[u] = PK(spx[i0], spx[i1]);
        py2[u] = PK(spy[i0], spy[i1]);
        pz2[u] = PK(spz[i0], spz[i1]);
        dd[2*u] = 1e10f; dd[2*u+1] = 1e10f;
    }
    float lx = spx[0], ly = spy[0], lz = spz[0];
    if (tid == 0) {
        float qq = __fadd_rn(__fadd_rn(__fmul_rn(lx,lx), __fmul_rn(ly,ly)), __fmul_rn(lz,lz));
        g_q[b*Mz] = make_float4(lx, ly, lz, qq);
    }

    for (int t = 1; t < Mz; ++t) {
        const ull nx2 = PK(-lx,-lx), ny2 = PK(-ly,-ly), nz2 = PK(-lz,-lz);
        float bv = 0.0f;                               // dd >= 0 always
#pragma unroll
        for (int u = 0; u < 16; ++u) {
            // FMA-contracted: dx*dx + dy*dy + dz*dz (ulp-level vs reference; decisions robust)
            ull dx2 = ADD2(px2[u], nx2);
            ull dy2 = ADD2(py2[u], ny2);
            ull dz2 = ADD2(pz2[u], nz2);
            ull d2  = MUL2(dx2, dx2);
            d2 = FMA2(dy2, dy2, d2);
            d2 = FMA2(dz2, dz2, d2);
            float d0, d1; UPK(d2, d0, d1);
            float n0 = fminf(dd[2*u],   d0);
            float n1 = fminf(dd[2*u+1], d1);
            dd[2*u] = n0; dd[2*u+1] = n1;
            bv = fmaxf(bv, fmaxf(n0, n1));
        }
        // warp max via single REDUX (nonneg float bits are monotonic as u32)
        unsigned wmax = __reduce_max_sync(0xffffffffu, __float_as_uint(bv));
        if ((tid & 31) == 0) s_bv[tid >> 5] = wmax;
        __syncthreads();                               // bar 1
        unsigned gb = s_bv[0];
#pragma unroll
        for (int w = 1; w < 8; ++w) gb = umax(gb, s_bv[w]);
        const float bvg = __uint_as_float(gb);
        const int buf = t & 1;
        if (tid == 0) s_wi[buf^1] = 0xFFFFFFFFu;       // reset next-step buffer
        if (__float_as_uint(bv) == gb) {               // only winning threads scan
            unsigned best = 0xFFFFFFFFu;
#pragma unroll
            for (int u = 31; u >= 0; --u)              // descending: last write = lowest index
                if (dd[u] == bvg) best = (unsigned)(tid + u*256);
            atomicMin(&s_wi[buf], best);               // lowest global index wins ties
        }
        __syncthreads();                               // bar 2
        const unsigned wi = s_wi[buf];
        lx = spx[wi]; ly = spy[wi]; lz = spz[wi];
        if (tid == 0) {
            float qq = __fadd_rn(__fadd_rn(__fmul_rn(lx,lx), __fmul_rn(ly,ly)), __fmul_rn(lz,lz));
            g_q[b*Mz + t] = make_float4(lx, ly, lz, qq);
        }
    }
}

// ================= kNN: 256 queries/block x 8 point-slices, packed FMA distances =============
__global__ void __launch_bounds__(256) knn_kernel(const float* __restrict__ p) {
    __shared__ ull spt[SLEN/2][4];      // per pair: x2,y2,z2,w2 (16kB)
    const int tid = threadIdx.x;
    const int qi = blockIdx.x*256 + tid;
    const int b  = qi >> 11;
    const float* pb = p + (size_t)b*Nz*3;
    const int t0 = blockIdx.y * SLEN;

    for (int i = tid; i < SLEN/2; i += 256) {
        int i0 = t0 + 2*i, i1 = i0 + 1;
        float x0 = pb[3*i0+0], y0 = pb[3*i0+1], z0 = pb[3*i0+2];
        float x1 = pb[3*i1+0], y1 = pb[3*i1+1], z1 = pb[3*i1+2];
        float w0 = __fadd_rn(__fadd_rn(__fmul_rn(x0,x0), __fmul_rn(y0,y0)), __fmul_rn(z0,z0));
        float w1 = __fadd_rn(__fadd_rn(__fmul_rn(x1,x1), __fmul_rn(y1,y1)), __fmul_rn(z1,z1));
        spt[i][0] = PK(x0,x1); spt[i][1] = PK(y0,y1);
        spt[i][2] = PK(z0,z1); spt[i][3] = PK(w0,w1);
    }
    __syncthreads();

    const float4 q = g_q[qi];
    const ull qx2 = PK(q.x,q.x), qy2 = PK(q.y,q.y), qz2 = PK(q.z,q.z);
    const ull qw2 = PK(q.w,q.w), n2 = PK(-2.0f,-2.0f);

    float nd[Kz]; int ni[Kz];
#pragma unroll
    for (int j = 0; j < Kz; ++j) { nd[j] = 1e30f; ni[j] = 0; }
    float wk = 1e30f;

    for (int u = 0; u < SLEN/2; ++u) {
        const ulonglong2* r = (const ulonglong2*)spt[u];
        ulonglong2 r0 = r[0], r1 = r[1];
        // d = (qq + pp) + (-2)*dot, dot FMA-accumulated (matches reference einsum in spirit)
        ull a2 = MUL2(qx2, r0.x);
        a2 = FMA2(qy2, r0.y, a2);
        a2 = FMA2(qz2, r1.x, a2);
        ull a3 = ADD2(qw2, r1.y);
        ull d2 = FMA2(a2, n2, a3);
        float d0, d1; UPK(d2, d0, d1);
        if (d0 < wk) {
            float cd = d0; int ci = t0 + 2*u;
#pragma unroll
            for (int j = 0; j < Kz; ++j)
                if (cd < nd[j]) { float td = nd[j]; int ti = ni[j]; nd[j] = cd; ni[j] = ci; cd = td; ci = ti; }
            wk = nd[Kz-1];
        }
        if (d1 < wk) {
            float cd = d1; int ci = t0 + 2*u + 1;
#pragma unroll
            for (int j = 0; j < Kz; ++j)
                if (cd < nd[j]) { float td = nd[j]; int ti = ni[j]; nd[j] = cd; ni[j] = ci; cd = td; ci = ti; }
            wk = nd[Kz-1];
        }
    }
    const size_t base = ((size_t)qi*NSLICE + blockIdx.y)*Kz;
#pragma unroll
    for (int j = 0; j < Kz; ++j) { g_kd[base+j] = nd[j]; g_ki[base+j] = ni[j]; }
}

// ---- exact 8-way merge of per-slice sorted (d, idx) lists -> global top-20 ----
__global__ void __launch_bounds__(64) kmerge_kernel() {
    const int qi = blockIdx.x*64 + threadIdx.x;
    float dc[NSLICE]; int ic[NSLICE]; int h[NSLICE];
#pragma unroll
    for (int s = 0; s < NSLICE; ++s) {
        size_t base = ((size_t)qi*NSLICE + s)*Kz;
        dc[s] = g_kd[base]; ic[s] = g_ki[base]; h[s] = 0;
    }
    for (int j = 0; j < Kz; ++j) {
        int bs = 0;
#pragma unroll
        for (int s = 1; s < NSLICE; ++s)
            if (dc[s] < dc[bs] || (dc[s] == dc[bs] && ic[s] < ic[bs])) bs = s;
        g_nidx[(size_t)qi*Kz + j] = ic[bs];
        h[bs]++;
        if (h[bs] < Kz) {
            size_t off = ((size_t)qi*NSLICE + bs)*Kz + h[bs];
            dc[bs] = g_kd[off]; ic[bs] = g_ki[off];
        } else { dc[bs] = 3.0e38f; ic[bs] = 0x7FFFFFFF; }
    }
}

// ====== conv1: 1 thread = 1 group-point, [6->64] matvec + leaky + fused BN stats ======
__global__ void __launch_bounds__(128) conv1_kernel(const float* __restrict__ p,
                                                    const float* __restrict__ W1) {
    __shared__ float sWc[64][8];        // [c][j], 2 broadcast loads per channel
    __shared__ float so[128*68];        // staged outputs (68-pad: 16B-aligned rows)
    __shared__ float sps[2][64], sqs[2][64];
    const int tid = threadIdx.x;
    if (tid < 64) {
#pragma unroll
        for (int j = 0; j < 6; ++j) sWc[tid][j] = W1[tid*6 + j];
        sWc[tid][6] = 0.f; sWc[tid][7] = 0.f;
    }
    const int gp0 = blockIdx.x * 128;
    const int gp = gp0 + tid;
    const int m = (gp / Kz) % Mz;
    const int b = gp / (Kz*Mz);
    const int nid = g_nidx[gp];
    const float* pr = p + ((size_t)b*Nz + nid)*3;
    float gx = pr[0], gy = pr[1], gz = pr[2];
    float4 q = g_q[b*Mz + m];
    float f0 = __fsub_rn(gx, q.x), f1 = __fsub_rn(gy, q.y), f2 = __fsub_rn(gz, q.z);
    __syncthreads();
#pragma unroll 4
    for (int c = 0; c < 64; ++c) {
        float4 w0 = *(const float4*)&sWc[c][0];
        float2 w1 = *(const float2*)&sWc[c][4];
        float acc = w0.x * f0;
        acc = fmaf(w0.y, f1, acc);
        acc = fmaf(w0.z, f2, acc);
        acc = fmaf(w0.w, gx, acc);
        acc = fmaf(w1.x, gy, acc);
        acc = fmaf(w1.y, gz, acc);
        so[tid*68 + c] = (acc >= 0.f) ? acc : 0.2f*acc;
    }
    __syncthreads();
    // fused BN stats partials
    {
        int c = tid & 63, h = tid >> 6;
        float s = 0.f, s2 = 0.f;
#pragma unroll 8
        for (int r = h*64; r < h*64 + 64; ++r) {
            float v = so[r*68 + c];
            s += v; s2 = fmaf(v, v, s2);
        }
        sps[h][c] = s; sqs[h][c] = s2;
    }
    __syncthreads();
    if (tid < 64) {
        atomicAdd(&g_sum[tid],      (double)(sps[0][tid] + sps[1][tid]));
        atomicAdd(&g_sum[64 + tid], (double)(sqs[0][tid] + sqs[1][tid]));
    }
    // coalesced writeout
    for (int idx = tid; idx < 2048; idx += 128) {
        int row = idx >> 4, sg = idx & 15;
        float4 v = *(const float4*)&so[row*68 + sg*4];
        *(float4*)(g_x1 + (size_t)(gp0 + row)*64 + sg*4) = v;
    }
}

// ======== conv2/3: FFMA2 [64->64] matvec, 4 pts/thread, fused BN stats ========
#define WJ 10
#define WCG (64*WJ + 4)
__global__ void __launch_bounds__(128) conv_kernel(int in_sel, const float* __restrict__ W,
                                                   int aff_stage) {
    const float* xin = in_sel ? g_x2 : g_x1;
    float*      xout = in_sel ? g_x1 : g_x2;
    __shared__ ull  sw[4*WCG];
    __shared__ float sx[128][65];
    __shared__ float sa[64], sc[64];
    __shared__ float ssumW[4*64], ssqW[4*64];
    const int tid = threadIdx.x;
    const int ww = tid >> 5, lane = tid & 31;

    for (int k = tid; k < 2048; k += 128) {
        int cgk = k >> 9, rem = k & 511, j = rem >> 3, qq = rem & 7;
        int c0 = cgk*16 + 2*qq;
        sw[cgk*WCG + j*WJ + qq] = PK(W[c0*64 + j], W[(c0+1)*64 + j]);
    }
    if (tid < 64) {
        sa[tid] = g_aff[aff_stage*128 + tid];
        sc[tid] = g_aff[aff_stage*128 + 64 + tid];
    }
    __syncthreads();
    const int p0 = blockIdx.x * 128;
    for (int idx = tid; idx < 8192; idx += 128) {
        int j = idx & 63;
        float v = xin[(size_t)p0*64 + idx];
        sx[idx >> 6][j] = fmaf(sa[j], v, sc[j]);
    }
    __syncthreads();

    const int ptb = tid >> 2, cg = tid & 3;
    const ull* wbase = &sw[cg*WCG];
    ull acc[4][8];
#pragma unroll
    for (int k = 0; k < 4; ++k)
#pragma unroll
        for (int qq = 0; qq < 8; ++qq) acc[k][qq] = 0ull;

    for (int j = 0; j < 64; ++j) {
        const ulonglong2* wr = (const ulonglong2*)(wbase + j*WJ);
        ulonglong2 w01 = wr[0], w23 = wr[1], w45 = wr[2], w67 = wr[3];
        ull wv[8] = {w01.x, w01.y, w23.x, w23.y, w45.x, w45.y, w67.x, w67.y};
#pragma unroll
        for (int k = 0; k < 4; ++k) {
            float xv = sx[ptb + 32*k][j];
            ull xv2 = PK(xv, xv);
#pragma unroll
            for (int qq = 0; qq < 8; ++qq)
                acc[k][qq] = FMA2(wv[qq], xv2, acc[k][qq]);
        }
    }
    float sacc[16], sqacc[16];
#pragma unroll
    for (int i = 0; i < 16; ++i) { sacc[i] = 0.f; sqacc[i] = 0.f; }
#pragma unroll
    for (int k = 0; k < 4; ++k) {
        float o[16];
#pragma unroll
        for (int qq = 0; qq < 8; ++qq) {
            float lo, hi; UPK(acc[k][qq], lo, hi);
            o[2*qq]   = (lo >= 0.f) ? lo : 0.2f*lo;
            o[2*qq+1] = (hi >= 0.f) ? hi : 0.2f*hi;
        }
#pragma unroll
        for (int i = 0; i < 16; ++i) {
            sacc[i] += o[i];
            sqacc[i] = fmaf(o[i], o[i], sqacc[i]);
        }
        float4* op = (float4*)(xout + (size_t)(p0 + ptb + 32*k)*64 + cg*16);
#pragma unroll
        for (int v4 = 0; v4 < 4; ++v4)
            op[v4] = make_float4(o[4*v4], o[4*v4+1], o[4*v4+2], o[4*v4+3]);
    }
    // reduce over the 8 same-cg lanes in this warp (xor 4,8,16)
#pragma unroll
    for (int o = 4; o <= 16; o <<= 1) {
#pragma unroll
        for (int i = 0; i < 16; ++i) {
            sacc[i]  += __shfl_xor_sync(0xffffffffu, sacc[i],  o);
            sqacc[i] += __shfl_xor_sync(0xffffffffu, sqacc[i], o);
        }
    }
    if (lane < 4) {
#pragma unroll
        for (int i = 0; i < 16; ++i) {
            ssumW[ww*64 + lane*16 + i] = sacc[i];
            ssqW [ww*64 + lane*16 + i] = sqacc[i];
        }
    }
    __syncthreads();
    if (tid < 64) {
        float S = 0.f, Q = 0.f;
#pragma unroll
        for (int v = 0; v < 4; ++v) { S += ssumW[v*64 + tid]; Q += ssqW[v*64 + tid]; }
        atomicAdd(&g_sum[tid],      (double)S);
        atomicAdd(&g_sum[64 + tid], (double)Q);
    }
}

// ---------------- BN finalize: affine a,c; re-zeroes accumulators for next stage/replay ------
__global__ void bnfin_kernel(int stage, const float* __restrict__ g, const float* __restrict__ bb) {
    const int c = threadIdx.x;   // 64 threads
    const double cnt = (double)PTS;
    double mean = g_sum[c] / cnt;
    double var  = g_sum[64 + c] / cnt - mean*mean;
    double inv  = 1.0 / sqrt(var + 1e-5);
    float a  = (float)((double)g[c] * inv);
    float cc = (float)((double)bb[c] - (double)a * mean);
    g_aff[stage*128 + c]      = a;
    g_aff[stage*128 + 64 + c] = cc;
    g_sum[c] = 0.0; g_sum[64 + c] = 0.0;
}

// ---------------- final: apply BN3 affine, max over K ----------------
__global__ void __launch_bounds__(256) maxk_kernel(float* __restrict__ out) {
    const int t = blockIdx.x*256 + threadIdx.x;      // [0, B*M*64)
    const int c = t & 63;
    const int m = (t >> 6) & 2047;
    const int b = t >> 17;
    const float* base = g_x1 + ((size_t)(b*Mz + m)*Kz)*64 + c;
    const float a  = g_aff[2*128 + c];
    const float cc = g_aff[2*128 + 64 + c];
    float mx = -1e30f;
#pragma unroll
    for (int k = 0; k < Kz; ++k) {
        float v = fmaf(a, base[(size_t)k*64], cc);
        mx = fmaxf(mx, v);
    }
    out[((size_t)(b*64 + c))*Mz + m] = mx;
}

// ---------------- launch ----------------
extern "C" void kernel_launch(void* const* d_in, const int* in_sizes, int n_in,
                              void* d_out, int out_size) {
    (void)in_sizes; (void)n_in; (void)out_size;
    const float* p  = (const float*)d_in[0];
    const float* W1 = (const float*)d_in[1];
    const float* g1 = (const float*)d_in[2];
    const float* b1 = (const float*)d_in[3];
    const float* W2 = (const float*)d_in[4];
    const float* g2 = (const float*)d_in[5];
    const float* b2 = (const float*)d_in[6];
    const float* W3 = (const float*)d_in[7];
    const float* g3 = (const float*)d_in[8];
    const float* b3 = (const float*)d_in[9];
    float* out = (float*)d_out;

    cudaFuncSetAttribute(fps_kernel, cudaFuncAttributeMaxDynamicSharedMemorySize, 3*Nz*4);

    fps_kernel<<<Bz, 256, 3*Nz*4>>>(p);
    knn_kernel<<<dim3((Bz*Mz)/256, NSLICE), 256>>>(p);
    kmerge_kernel<<<(Bz*Mz)/64, 64>>>();
    conv1_kernel<<<PTS/128, 128>>>(p, W1);
    bnfin_kernel<<<1, 64>>>(0, g1, b1);
    conv_kernel<<<PTS/128, 128>>>(0, W2, 0);
    bnfin_kernel<<<1, 64>>>(1, g2, b2);
    conv_kernel<<<PTS/128, 128>>>(1, W3, 1);
    bnfin_kernel<<<1, 64>>>(2, g3, b3);
    maxk_kernel<<<(Bz*Mz*Cz)/256, 256>>>(out);
}

// round 10
// speedup vs baseline: 1.3197x; 1.0886x over previous
#include <cuda_runtime.h>

#define Bz 4
#define Nz 8192
#define Mz 2048
#define Kz 20
#define Cz 64
#define PTS (Bz*Mz*Kz)   // 163840
#define NSLICE 8
#define SLEN 1024
#define NWORK 144
#define FUSED_SMEM (3*Nz*4)   // 96kB (FPS points; workers use 16kB of it as tile)

typedef unsigned long long ull;

// ---------------- packed f32x2 helpers (sm_100+: add/mul/fma only) ----------------
__device__ __forceinline__ ull PK(float lo, float hi) {
    ull r; asm("mov.b64 %0, {%1,%2};" : "=l"(r) : "f"(lo), "f"(hi)); return r;
}
__device__ __forceinline__ void UPK(ull v, float& lo, float& hi) {
    asm("mov.b64 {%0,%1}, %2;" : "=f"(lo), "=f"(hi) : "l"(v));
}
__device__ __forceinline__ ull ADD2(ull a, ull b) {
    ull r; asm("add.rn.f32x2 %0, %1, %2;" : "=l"(r) : "l"(a), "l"(b)); return r;
}
__device__ __forceinline__ ull MUL2(ull a, ull b) {
    ull r; asm("mul.rn.f32x2 %0, %1, %2;" : "=l"(r) : "l"(a), "l"(b)); return r;
}
__device__ __forceinline__ ull FMA2(ull a, ull b, ull c) {
    ull r; asm("fma.rn.f32x2 %0, %1, %2, %3;" : "=l"(r) : "l"(a), "l"(b), "l"(c)); return r;
}

// ---------------- scratch (static device globals; no allocation) ----------------
__device__ float4 g_q[Bz*Mz];                    // sampled pts: x,y,z,|q|^2
__device__ int    g_nidx[Bz*Mz*Kz];              // final knn indices
__device__ float  g_kd[Bz*Mz*NSLICE*Kz];         // per-slice partial top-20 dists
__device__ int    g_ki[Bz*Mz*NSLICE*Kz];         // per-slice partial top-20 idx
__device__ float  g_x1[(size_t)PTS*Cz];          // ~42MB
__device__ float  g_x2[(size_t)PTS*Cz];          // ~42MB
__device__ double g_sum[2*Cz];                   // per-channel sum / sumsq (re-zeroed by bnfin)
__device__ float  g_aff[3*2*Cz];                 // per-stage BN affine: a[64], c[64]
__device__ volatile unsigned g_prog[Bz];         // FPS progress per batch (handshake)

extern __shared__ float fused_sm[];

// ===== FPS role: 256 thr, 32 pts/thread, packed FMA distances, tree max, REDUX ===============
__device__ void fps_body(const float* __restrict__ p, int b) {
    const int tid = threadIdx.x;
    const float* pb = p + (size_t)b*Nz*3;
    float* spx = fused_sm; float* spy = fused_sm + Nz; float* spz = fused_sm + 2*Nz;
    __shared__ unsigned s_bv[8];
    __shared__ unsigned s_wi[2];

    for (int i = tid; i < Nz; i += 256) {
        spx[i] = pb[3*i+0]; spy[i] = pb[3*i+1]; spz[i] = pb[3*i+2];
    }
    if (tid == 0) { s_wi[0] = 0xFFFFFFFFu; s_wi[1] = 0xFFFFFFFFu; }
    __syncthreads();

    ull px2[16], py2[16], pz2[16];
    float dd[32];
#pragma unroll
    for (int u = 0; u < 16; ++u) {
        int i0 = tid + (2*u)*256, i1 = i0 + 256;
        px2[u] = PK(spx[i0], spx[i1]);
        py2[u] = PK(spy[i0], spy[i1]);
        pz2[u] = PK(spz[i0], spz[i1]);
        dd[2*u] = 1e10f; dd[2*u+1] = 1e10f;
    }
    float lx = spx[0], ly = spy[0], lz = spz[0];
    if (tid == 0) {
        float qq = __fadd_rn(__fadd_rn(__fmul_rn(lx,lx), __fmul_rn(ly,ly)), __fmul_rn(lz,lz));
        g_q[b*Mz] = make_float4(lx, ly, lz, qq);
    }

    for (int t = 1; t < Mz; ++t) {
        const ull nx2 = PK(-lx,-lx), ny2 = PK(-ly,-ly), nz2 = PK(-lz,-lz);
        float m[16];
#pragma unroll
        for (int u = 0; u < 16; ++u) {
            ull dx2 = ADD2(px2[u], nx2);
            ull dy2 = ADD2(py2[u], ny2);
            ull dz2 = ADD2(pz2[u], nz2);
            ull d2  = MUL2(dx2, dx2);
            d2 = FMA2(dy2, dy2, d2);
            d2 = FMA2(dz2, dz2, d2);
            float d0, d1; UPK(d2, d0, d1);
            float n0 = fminf(dd[2*u],   d0);
            float n1 = fminf(dd[2*u+1], d1);
            dd[2*u] = n0; dd[2*u+1] = n1;
            m[u] = fmaxf(n0, n1);            // independent per u (no serial chain)
        }
        // depth-4 max tree (exact; max reassociation cannot change the result)
#pragma unroll
        for (int s = 8; s; s >>= 1)
#pragma unroll
            for (int i = 0; i < s; ++i) m[i] = fmaxf(m[i], m[i+s]);
        const float bv = m[0];
        unsigned wmax = __reduce_max_sync(0xffffffffu, __float_as_uint(bv));
        if ((tid & 31) == 0) s_bv[tid >> 5] = wmax;
        __syncthreads();                               // bar 1
        unsigned gb = s_bv[0];
#pragma unroll
        for (int w = 1; w < 8; ++w) gb = umax(gb, s_bv[w]);
        const float bvg = __uint_as_float(gb);
        const int buf = t & 1;
        if (tid == 0) s_wi[buf^1] = 0xFFFFFFFFu;       // reset next-step buffer
        if (__float_as_uint(bv) == gb) {               // only winning threads scan
            unsigned best = 0xFFFFFFFFu;
#pragma unroll
            for (int u = 31; u >= 0; --u)              // descending: last write = lowest index
                if (dd[u] == bvg) best = (unsigned)(tid + u*256);
            atomicMin(&s_wi[buf], best);               // lowest global index wins ties
        }
        __syncthreads();                               // bar 2
        const unsigned wi = s_wi[buf];
        lx = spx[wi]; ly = spy[wi]; lz = spz[wi];
        if (tid == 0) {
            float qq = __fadd_rn(__fadd_rn(__fmul_rn(lx,lx), __fmul_rn(ly,ly)), __fmul_rn(lz,lz));
            g_q[b*Mz + t] = make_float4(lx, ly, lz, qq);
            if ((t & 63) == 63) {                      // t=2047 publishes 2048
                __threadfence();
                g_prog[b] = (unsigned)(t + 1);
            }
        }
    }
}

// ===== kNN worker role: up to 2 units of (query-block qb, slice sl); spin on FPS progress ====
__device__ void knn_unit(const float* __restrict__ p, int e) {
    ull (*spt)[4] = (ull(*)[4])fused_sm;    // 16kB tile
    const int tid = threadIdx.x;
    const int qb = e & 31, sl = e >> 5;
    const int b  = qb >> 3;
    const float* pb = p + (size_t)b*Nz*3;
    const int t0 = sl * SLEN;

    for (int i = tid; i < SLEN/2; i += 256) {
        int i0 = t0 + 2*i, i1 = i0 + 1;
        float x0 = pb[3*i0+0], y0 = pb[3*i0+1], z0 = pb[3*i0+2];
        float x1 = pb[3*i1+0], y1 = pb[3*i1+1], z1 = pb[3*i1+2];
        float w0 = __fadd_rn(__fadd_rn(__fmul_rn(x0,x0), __fmul_rn(y0,y0)), __fmul_rn(z0,z0));
        float w1 = __fadd_rn(__fadd_rn(__fmul_rn(x1,x1), __fmul_rn(y1,y1)), __fmul_rn(z1,z1));
        spt[i][0] = PK(x0,x1); spt[i][1] = PK(y0,y1);
        spt[i][2] = PK(z0,z1); spt[i][3] = PK(w0,w1);
    }
    if (tid == 0) {                                   // sleep-spin: producer is guaranteed resident
        const unsigned need = ((unsigned)(qb & 7) + 1u) * 256u;
        while (g_prog[b] < need) __nanosleep(256);
        __threadfence();
    }
    __syncthreads();

    const int qi = qb*256 + tid;
    const float4 q = g_q[qi];
    const ull qx2 = PK(q.x,q.x), qy2 = PK(q.y,q.y), qz2 = PK(q.z,q.z);
    const ull qw2 = PK(q.w,q.w), n2 = PK(-2.0f,-2.0f);

    float nd[Kz]; int ni[Kz];
#pragma unroll
    for (int j = 0; j < Kz; ++j) { nd[j] = 1e30f; ni[j] = 0; }
    float wk = 1e30f;

    for (int u = 0; u < SLEN/2; ++u) {
        const ulonglong2* r = (const ulonglong2*)spt[u];
        ulonglong2 r0 = r[0], r1 = r[1];
        ull a2 = MUL2(qx2, r0.x);
        a2 = FMA2(qy2, r0.y, a2);
        a2 = FMA2(qz2, r1.x, a2);
        ull a3 = ADD2(qw2, r1.y);
        ull d2 = FMA2(a2, n2, a3);
        float d0, d1; UPK(d2, d0, d1);
        if (d0 < wk) {
            float cd = d0; int ci = t0 + 2*u;
#pragma unroll
            for (int j = 0; j < Kz; ++j)
                if (cd < nd[j]) { float td = nd[j]; int ti = ni[j]; nd[j] = cd; ni[j] = ci; cd = td; ci = ti; }
            wk = nd[Kz-1];
        }
        if (d1 < wk) {
            float cd = d1; int ci = t0 + 2*u + 1;
#pragma unroll
            for (int j = 0; j < Kz; ++j)
                if (cd < nd[j]) { float td = nd[j]; int ti = ni[j]; nd[j] = cd; ni[j] = ci; cd = td; ci = ti; }
            wk = nd[Kz-1];
        }
    }
    const size_t base = ((size_t)qi*NSLICE + sl)*Kz;
#pragma unroll
    for (int j = 0; j < Kz; ++j) { g_kd[base+j] = nd[j]; g_ki[base+j] = ni[j]; }
}

// ===== fused kernel: 148 blocks = one wave, all resident -> spin cannot deadlock ==============
__global__ void __launch_bounds__(256,1) fused_kernel(const float* __restrict__ p) {
    if (blockIdx.x < Bz) {
        fps_body(p, blockIdx.x);
    } else {
        const int w = blockIdx.x - Bz;       // 0..143
        knn_unit(p, w);
        if (w + NWORK < 256) {
            __syncthreads();                 // protect smem tile reuse
            knn_unit(p, w + NWORK);
        }
    }
}

// ---- exact 8-way merge of per-slice sorted (d, idx) lists -> global top-20 ----
__global__ void __launch_bounds__(64) kmerge_kernel() {
    const int qi = blockIdx.x*64 + threadIdx.x;
    float dc[NSLICE]; int ic[NSLICE]; int h[NSLICE];
#pragma unroll
    for (int s = 0; s < NSLICE; ++s) {
        size_t base = ((size_t)qi*NSLICE + s)*Kz;
        dc[s] = g_kd[base]; ic[s] = g_ki[base]; h[s] = 0;
    }
    for (int j = 0; j < Kz; ++j) {
        int bs = 0;
#pragma unroll
        for (int s = 1; s < NSLICE; ++s)
            if (dc[s] < dc[bs] || (dc[s] == dc[bs] && ic[s] < ic[bs])) bs = s;
        g_nidx[(size_t)qi*Kz + j] = ic[bs];
        h[bs]++;
        if (h[bs] < Kz) {
            size_t off = ((size_t)qi*NSLICE + bs)*Kz + h[bs];
            dc[bs] = g_kd[off]; ic[bs] = g_ki[off];
        } else { dc[bs] = 3.0e38f; ic[bs] = 0x7FFFFFFF; }
    }
}

// ====== conv1: 1 thread = 1 group-point, [6->64] matvec + leaky + fused BN stats ======
__global__ void __launch_bounds__(128) conv1_kernel(const float* __restrict__ p,
                                                    const float* __restrict__ W1) {
    __shared__ float sWc[64][8];
    __shared__ float so[128*68];
    __shared__ float sps[2][64], sqs[2][64];
    const int tid = threadIdx.x;
    if (tid < 64) {
#pragma unroll
        for (int j = 0; j < 6; ++j) sWc[tid][j] = W1[tid*6 + j];
        sWc[tid][6] = 0.f; sWc[tid][7] = 0.f;
    }
    const int gp0 = blockIdx.x * 128;
    const int gp = gp0 + tid;
    const int m = (gp / Kz) % Mz;
    const int b = gp / (Kz*Mz);
    const int nid = g_nidx[gp];
    const float* pr = p + ((size_t)b*Nz + nid)*3;
    float gx = pr[0], gy = pr[1], gz = pr[2];
    float4 q = g_q[b*Mz + m];
    float f0 = __fsub_rn(gx, q.x), f1 = __fsub_rn(gy, q.y), f2 = __fsub_rn(gz, q.z);
    __syncthreads();
#pragma unroll 4
    for (int c = 0; c < 64; ++c) {
        float4 w0 = *(const float4*)&sWc[c][0];
        float2 w1 = *(const float2*)&sWc[c][4];
        float acc = w0.x * f0;
        acc = fmaf(w0.y, f1, acc);
        acc = fmaf(w0.z, f2, acc);
        acc = fmaf(w0.w, gx, acc);
        acc = fmaf(w1.x, gy, acc);
        acc = fmaf(w1.y, gz, acc);
        so[tid*68 + c] = (acc >= 0.f) ? acc : 0.2f*acc;
    }
    __syncthreads();
    {
        int c = tid & 63, h = tid >> 6;
        float s = 0.f, s2 = 0.f;
#pragma unroll 8
        for (int r = h*64; r < h*64 + 64; ++r) {
            float v = so[r*68 + c];
            s += v; s2 = fmaf(v, v, s2);
        }
        sps[h][c] = s; sqs[h][c] = s2;
    }
    __syncthreads();
    if (tid < 64) {
        atomicAdd(&g_sum[tid],      (double)(sps[0][tid] + sps[1][tid]));
        atomicAdd(&g_sum[64 + tid], (double)(sqs[0][tid] + sqs[1][tid]));
    }
    for (int idx = tid; idx < 2048; idx += 128) {
        int row = idx >> 4, sg = idx & 15;
        float4 v = *(const float4*)&so[row*68 + sg*4];
        *(float4*)(g_x1 + (size_t)(gp0 + row)*64 + sg*4) = v;
    }
}

// ======== conv2/3: FFMA2 [64->64] matvec, 4 pts/thread, fused BN stats ========
#define WJ 10
#define WCG (64*WJ + 4)
__global__ void __launch_bounds__(128) conv_kernel(int in_sel, const float* __restrict__ W,
                                                   int aff_stage) {
    const float* xin = in_sel ? g_x2 : g_x1;
    float*      xout = in_sel ? g_x1 : g_x2;
    __shared__ ull  sw[4*WCG];
    __shared__ float sx[128][65];
    __shared__ float sa[64], sc[64];
    __shared__ float ssumW[4*64], ssqW[4*64];
    const int tid = threadIdx.x;
    const int ww = tid >> 5, lane = tid & 31;

    for (int k = tid; k < 2048; k += 128) {
        int cgk = k >> 9, rem = k & 511, j = rem >> 3, qq = rem & 7;
        int c0 = cgk*16 + 2*qq;
        sw[cgk*WCG + j*WJ + qq] = PK(W[c0*64 + j], W[(c0+1)*64 + j]);
    }
    if (tid < 64) {
        sa[tid] = g_aff[aff_stage*128 + tid];
        sc[tid] = g_aff[aff_stage*128 + 64 + tid];
    }
    __syncthreads();
    const int p0 = blockIdx.x * 128;
    for (int idx = tid; idx < 8192; idx += 128) {
        int j = idx & 63;
        float v = xin[(size_t)p0*64 + idx];
        sx[idx >> 6][j] = fmaf(sa[j], v, sc[j]);
    }
    __syncthreads();

    const int ptb = tid >> 2, cg = tid & 3;
    const ull* wbase = &sw[cg*WCG];
    ull acc[4][8];
#pragma unroll
    for (int k = 0; k < 4; ++k)
#pragma unroll
        for (int qq = 0; qq < 8; ++qq) acc[k][qq] = 0ull;

    for (int j = 0; j < 64; ++j) {
        const ulonglong2* wr = (const ulonglong2*)(wbase + j*WJ);
        ulonglong2 w01 = wr[0], w23 = wr[1], w45 = wr[2], w67 = wr[3];
        ull wv[8] = {w01.x, w01.y, w23.x, w23.y, w45.x, w45.y, w67.x, w67.y};
#pragma unroll
        for (int k = 0; k < 4; ++k) {
            float xv = sx[ptb + 32*k][j];
            ull xv2 = PK(xv, xv);
#pragma unroll
            for (int qq = 0; qq < 8; ++qq)
                acc[k][qq] = FMA2(wv[qq], xv2, acc[k][qq]);
        }
    }
    float sacc[16], sqacc[16];
#pragma unroll
    for (int i = 0; i < 16; ++i) { sacc[i] = 0.f; sqacc[i] = 0.f; }
#pragma unroll
    for (int k = 0; k < 4; ++k) {
        float o[16];
#pragma unroll
        for (int qq = 0; qq < 8; ++qq) {
            float lo, hi; UPK(acc[k][qq], lo, hi);
            o[2*qq]   = (lo >= 0.f) ? lo : 0.2f*lo;
            o[2*qq+1] = (hi >= 0.f) ? hi : 0.2f*hi;
        }
#pragma unroll
        for (int i = 0; i < 16; ++i) {
            sacc[i] += o[i];
            sqacc[i] = fmaf(o[i], o[i], sqacc[i]);
        }
        float4* op = (float4*)(xout + (size_t)(p0 + ptb + 32*k)*64 + cg*16);
#pragma unroll
        for (int v4 = 0; v4 < 4; ++v4)
            op[v4] = make_float4(o[4*v4], o[4*v4+1], o[4*v4+2], o[4*v4+3]);
    }
#pragma unroll
    for (int o = 4; o <= 16; o <<= 1) {
#pragma unroll
        for (int i = 0; i < 16; ++i) {
            sacc[i]  += __shfl_xor_sync(0xffffffffu, sacc[i],  o);
            sqacc[i] += __shfl_xor_sync(0xffffffffu, sqacc[i], o);
        }
    }
    if (lane < 4) {
#pragma unroll
        for (int i = 0; i < 16; ++i) {
            ssumW[ww*64 + lane*16 + i] = sacc[i];
            ssqW [ww*64 + lane*16 + i] = sqacc[i];
        }
    }
    __syncthreads();
    if (tid < 64) {
        float S = 0.f, Q = 0.f;
#pragma unroll
        for (int v = 0; v < 4; ++v) { S += ssumW[v*64 + tid]; Q += ssqW[v*64 + tid]; }
        atomicAdd(&g_sum[tid],      (double)S);
        atomicAdd(&g_sum[64 + tid], (double)Q);
    }
}

// ---------------- BN finalize ----------------
__global__ void bnfin_kernel(int stage, const float* __restrict__ g, const float* __restrict__ bb) {
    const int c = threadIdx.x;
    const double cnt = (double)PTS;
    double mean = g_sum[c] / cnt;
    double var  = g_sum[64 + c] / cnt - mean*mean;
    double inv  = 1.0 / sqrt(var + 1e-5);
    float a  = (float)((double)g[c] * inv);
    float cc = (float)((double)bb[c] - (double)a * mean);
    g_aff[stage*128 + c]      = a;
    g_aff[stage*128 + 64 + c] = cc;
    g_sum[c] = 0.0; g_sum[64 + c] = 0.0;
}

// ---------------- final: apply BN3 affine, max over K ----------------
__global__ void __launch_bounds__(256) maxk_kernel(float* __restrict__ out) {
    const int t = blockIdx.x*256 + threadIdx.x;
    const int c = t & 63;
    const int m = (t >> 6) & 2047;
    const int b = t >> 17;
    const float* base = g_x1 + ((size_t)(b*Mz + m)*Kz)*64 + c;
    const float a  = g_aff[2*128 + c];
    const float cc = g_aff[2*128 + 64 + c];
    float mx = -1e30f;
#pragma unroll
    for (int k = 0; k < Kz; ++k) {
        float v = fmaf(a, base[(size_t)k*64], cc);
        mx = fmaxf(mx, v);
    }
    out[((size_t)(b*64 + c))*Mz + m] = mx;
}

// ---------------- launch (single stream; fused FPS||kNN) ----------------
extern "C" void kernel_launch(void* const* d_in, const int* in_sizes, int n_in,
                              void* d_out, int out_size) {
    (void)in_sizes; (void)n_in; (void)out_size;
    const float* p  = (const float*)d_in[0];
    const float* W1 = (const float*)d_in[1];
    const float* g1 = (const float*)d_in[2];
    const float* b1 = (const float*)d_in[3];
    const float* W2 = (const float*)d_in[4];
    const float* g2 = (const float*)d_in[5];
    const float* b2 = (const float*)d_in[6];
    const float* W3 = (const float*)d_in[7];
    const float* g3 = (const float*)d_in[8];
    const float* b3 = (const float*)d_in[9];
    float* out = (float*)d_out;

    cudaFuncSetAttribute(fused_kernel, cudaFuncAttributeMaxDynamicSharedMemorySize, FUSED_SMEM);

    fused_kernel<<<Bz + NWORK, 256, FUSED_SMEM>>>(p);
    kmerge_kernel<<<(Bz*Mz)/64, 64>>>();
    conv1_kernel<<<PTS/128, 128>>>(p, W1);
    bnfin_kernel<<<1, 64>>>(0, g1, b1);
    conv_kernel<<<PTS/128, 128>>>(0, W2, 0);
    bnfin_kernel<<<1, 64>>>(1, g2, b2);
    conv_kernel<<<PTS/128, 128>>>(1, W3, 1);
    bnfin_kernel<<<1, 64>>>(2, g3, b3);
    maxk_kernel<<<(Bz*Mz*Cz)/256, 256>>>(out);
}